// round 15
// baseline (speedup 1.0000x reference)
#include <cuda_runtime.h>

#define NN   8192
#define DIN  256
#define KCOM 8

// ---------------- scratch (device globals; no allocations allowed) ----------
__device__ float g_inp[NN * DIN];     // F_ @ X
__device__ float g_h0 [NN * DIN];     // tanh layer 0
__device__ float g_h1 [NN * 128];     // tanh layer 1
__device__ float g_n2 [NN];           // row norms of E
__device__ float g_Fg [NN * KCOM];    // new_force @ members (flattened)
__device__ float g_d0p[64 * 1024];    // partial sums for d0 GEMV (deterministic)

typedef unsigned long long ull;

// ---------------- packed f32x2 helpers (Blackwell FFMA2 path) ---------------
__device__ __forceinline__ ull pack2(float lo, float hi) {
    ull u;
    asm("mov.b64 %0, {%1, %2};" : "=l"(u) : "f"(lo), "f"(hi));
    return u;
}
__device__ __forceinline__ void unpack2(ull u, float &lo, float &hi) {
    asm("mov.b64 {%0, %1}, %2;" : "=f"(lo), "=f"(hi) : "l"(u));
}
__device__ __forceinline__ ull fma2(ull a, ull b, ull c) {
    ull d;
    asm("fma.rn.f32x2 %0, %1, %2, %3;" : "=l"(d) : "l"(a), "l"(b), "l"(c));
    return d;
}

// ---------------- generic fp32 GEMM: C = act(A@B + bias) --------------------
// A[M,K], B[K,N], C[M,N] row-major. ACT: 0 = none, 1 = tanh.
template <int BM, int BN, int BK, int TM, int TN, int ACT>
__global__ void __launch_bounds__((BM / TM) * (BN / TN))
gemm_kernel(const float *__restrict__ A, const float *__restrict__ B,
            const float *__restrict__ bias, float *__restrict__ C,
            int M, int N, int K)
{
    constexpr int TX = BN / TN;
    constexpr int TY = BM / TM;
    constexpr int NT = TX * TY;
    static_assert((BM * BK) % (NT * 4) == 0, "A tile load");
    static_assert((BK * BN) % (NT * 4) == 0, "B tile load");
    static_assert(TN % 2 == 0, "packed pairs");

    __shared__ float As[BK][BM];
    __shared__ float Bs[BK][BN];

    const int tid = threadIdx.x;
    const int tx  = tid % TX;
    const int ty  = tid / TX;
    const int m0  = blockIdx.y * BM;
    const int n0  = blockIdx.x * BN;

    ull acc[TM][TN / 2];
#pragma unroll
    for (int r = 0; r < TM; r++)
#pragma unroll
        for (int p = 0; p < TN / 2; p++) acc[r][p] = 0ull;

    for (int k0 = 0; k0 < K; k0 += BK) {
        // load A tile (BM x BK), transposed into As[k][m]
#pragma unroll
        for (int l = tid * 4; l < BM * BK; l += NT * 4) {
            int r  = l / BK;
            int kk = l % BK;
            float4 v = *reinterpret_cast<const float4 *>(
                &A[(long long)(m0 + r) * K + k0 + kk]);
            As[kk + 0][r] = v.x;
            As[kk + 1][r] = v.y;
            As[kk + 2][r] = v.z;
            As[kk + 3][r] = v.w;
        }
        // load B tile (BK x BN)
#pragma unroll
        for (int l = tid * 4; l < BK * BN; l += NT * 4) {
            int kk = l / BN;
            int j  = l % BN;
            *reinterpret_cast<float4 *>(&Bs[kk][j]) =
                *reinterpret_cast<const float4 *>(
                    &B[(long long)(k0 + kk) * N + n0 + j]);
        }
        __syncthreads();

#pragma unroll
        for (int kk = 0; kk < BK; kk++) {
            float a[TM];
            ull   bp[TN / 2];
#pragma unroll
            for (int r = 0; r < TM; r++) a[r] = As[kk][ty * TM + r];
#pragma unroll
            for (int p = 0; p < TN / 2; p++) {
                float2 b2 = *reinterpret_cast<const float2 *>(&Bs[kk][tx * TN + 2 * p]);
                bp[p] = pack2(b2.x, b2.y);
            }
#pragma unroll
            for (int r = 0; r < TM; r++) {
                ull ap = pack2(a[r], a[r]);
#pragma unroll
                for (int p = 0; p < TN / 2; p++)
                    acc[r][p] = fma2(ap, bp[p], acc[r][p]);
            }
        }
        __syncthreads();
    }

    // epilogue
#pragma unroll
    for (int r = 0; r < TM; r++) {
        long long row = m0 + ty * TM + r;
#pragma unroll
        for (int p = 0; p < TN / 2; p++) {
            float x0, x1;
            unpack2(acc[r][p], x0, x1);
            int col = n0 + tx * TN + 2 * p;
            if (bias) { x0 += bias[col]; x1 += bias[col + 1]; }
            if (ACT == 1) { x0 = tanhf(x0); x1 = tanhf(x1); }
            C[row * N + col]     = x0;
            C[row * N + col + 1] = x1;
        }
    }
}

// ---------------- row norms of E (sequential fma, order matches dist) -------
__global__ void n2_kernel(const float *__restrict__ E, float *__restrict__ n2)
{
    int i = blockIdx.x * blockDim.x + threadIdx.x;
    if (i < NN) {
        const float *row = E + (long long)i * 64;
        float acc = 0.0f;
#pragma unroll
        for (int k = 0; k < 64; k++) acc = fmaf(row[k], row[k], acc);
        n2[i] = acc;
    }
}

// ---------------- fused pairwise-dist * path_forces --------------------------
// force[i,j] = (sq>0 ? sqrt(sq) : 0) * pf[i,j],  sq = n2[i]+n2[j]-2*<E_i,E_j>
__global__ void __launch_bounds__(256)
dist_kernel(const float *__restrict__ E, const float *__restrict__ n2,
            const float *__restrict__ pf, float *__restrict__ force)
{
    __shared__ float As[32][128];   // [k][i]
    __shared__ float Bs[32][128];   // [k][j]

    const int tid = threadIdx.x;
    const int tx  = tid % 16;
    const int ty  = tid / 16;
    const int i0  = blockIdx.y * 128;
    const int j0  = blockIdx.x * 128;

    ull acc[8][4];
#pragma unroll
    for (int r = 0; r < 8; r++)
#pragma unroll
        for (int p = 0; p < 4; p++) acc[r][p] = 0ull;

    for (int kc = 0; kc < 64; kc += 32) {
#pragma unroll
        for (int l = tid * 4; l < 128 * 32; l += 256 * 4) {
            int r = l / 32;
            int k = l % 32;
            float4 v = *reinterpret_cast<const float4 *>(&E[(long long)(i0 + r) * 64 + kc + k]);
            As[k + 0][r] = v.x; As[k + 1][r] = v.y; As[k + 2][r] = v.z; As[k + 3][r] = v.w;
            float4 w = *reinterpret_cast<const float4 *>(&E[(long long)(j0 + r) * 64 + kc + k]);
            Bs[k + 0][r] = w.x; Bs[k + 1][r] = w.y; Bs[k + 2][r] = w.z; Bs[k + 3][r] = w.w;
        }
        __syncthreads();

#pragma unroll
        for (int k = 0; k < 32; k++) {
            float a[8];
            ull   bp[4];
#pragma unroll
            for (int r = 0; r < 8; r++) a[r] = As[k][ty * 8 + r];
#pragma unroll
            for (int p = 0; p < 4; p++) {
                float2 b2 = *reinterpret_cast<const float2 *>(&Bs[k][tx * 8 + 2 * p]);
                bp[p] = pack2(b2.x, b2.y);
            }
#pragma unroll
            for (int r = 0; r < 8; r++) {
                ull ap = pack2(a[r], a[r]);
#pragma unroll
                for (int p = 0; p < 4; p++)
                    acc[r][p] = fma2(ap, bp[p], acc[r][p]);
            }
        }
        __syncthreads();
    }

    float n2i[8], n2j[8];
#pragma unroll
    for (int r = 0; r < 8; r++) n2i[r] = n2[i0 + ty * 8 + r];
#pragma unroll
    for (int c = 0; c < 8; c++) n2j[c] = n2[j0 + tx * 8 + c];

#pragma unroll
    for (int r = 0; r < 8; r++) {
        long long row = i0 + ty * 8 + r;
#pragma unroll
        for (int p = 0; p < 4; p++) {
            float d0, d1;
            unpack2(acc[r][p], d0, d1);
            float s0 = (n2i[r] + n2j[2 * p])     - 2.0f * d0;
            float s1 = (n2i[r] + n2j[2 * p + 1]) - 2.0f * d1;
            float dist0 = (s0 > 0.0f) ? sqrtf(s0) : 0.0f;
            float dist1 = (s1 > 0.0f) ? sqrtf(s1) : 0.0f;
            long long idx = row * NN + j0 + tx * 8 + 2 * p;
            float2 pfv = *reinterpret_cast<const float2 *>(&pf[idx]);
            float2 outv;
            outv.x = dist0 * pfv.x;
            outv.y = dist1 * pfv.y;
            *reinterpret_cast<float2 *>(&force[idx]) = outv;
        }
    }
}

// ---------------- Fg[i,k] = sum_j force[i,j] * members[j,k] ------------------
__global__ void __launch_bounds__(256)
fg_kernel(const float *__restrict__ force, const float *__restrict__ members,
          float *__restrict__ Fg)
{
    const int i   = blockIdx.x;
    const int tid = threadIdx.x;
    const float *frow = force + (long long)i * NN;

    float acc[8] = {0, 0, 0, 0, 0, 0, 0, 0};
    for (int j = tid; j < NN; j += 256) {
        float f   = frow[j];
        float4 m0 = *reinterpret_cast<const float4 *>(&members[j * 8]);
        float4 m1 = *reinterpret_cast<const float4 *>(&members[j * 8 + 4]);
        acc[0] = fmaf(f, m0.x, acc[0]);
        acc[1] = fmaf(f, m0.y, acc[1]);
        acc[2] = fmaf(f, m0.z, acc[2]);
        acc[3] = fmaf(f, m0.w, acc[3]);
        acc[4] = fmaf(f, m1.x, acc[4]);
        acc[5] = fmaf(f, m1.y, acc[5]);
        acc[6] = fmaf(f, m1.z, acc[6]);
        acc[7] = fmaf(f, m1.w, acc[7]);
    }
#pragma unroll
    for (int k = 0; k < 8; k++)
#pragma unroll
        for (int off = 16; off > 0; off >>= 1)
            acc[k] += __shfl_down_sync(0xffffffffu, acc[k], off);

    __shared__ float red[8][8];
    int lane = tid & 31, w = tid >> 5;
    if (lane == 0) {
#pragma unroll
        for (int k = 0; k < 8; k++) red[w][k] = acc[k];
    }
    __syncthreads();
    if (tid < 8) {
        float s = 0.0f;
#pragma unroll
        for (int w2 = 0; w2 < 8; w2++) s += red[w2][tid];
        Fg[i * 8 + tid] = s;
    }
}

// ---------------- d0 GEMV partials: d0p[chunk][c] = sum over 1024 rows -------
__global__ void __launch_bounds__(256)
d0_kernel(const float *__restrict__ Fg, const float *__restrict__ Wd0,
          float *__restrict__ d0p)
{
    __shared__ float sv[1024];
    const int tid = threadIdx.x;
    const int m0  = blockIdx.y * 1024;
    const int c   = blockIdx.x * 256 + tid;
#pragma unroll
    for (int s = 0; s < 4; s++) sv[tid + 256 * s] = Fg[m0 + tid + 256 * s];
    __syncthreads();

    float a0 = 0, a1 = 0, a2 = 0, a3 = 0;
    const float *W = Wd0 + (long long)m0 * 1024 + c;
    for (int m = 0; m < 1024; m += 4) {
        a0 = fmaf(sv[m + 0], W[(long long)(m + 0) * 1024], a0);
        a1 = fmaf(sv[m + 1], W[(long long)(m + 1) * 1024], a1);
        a2 = fmaf(sv[m + 2], W[(long long)(m + 2) * 1024], a2);
        a3 = fmaf(sv[m + 3], W[(long long)(m + 3) * 1024], a3);
    }
    d0p[blockIdx.y * 1024 + c] = (a0 + a1) + (a2 + a3);
}

// ---------------- tail: relu(d0)->relu(d1)->softmax -------------------------
__global__ void __launch_bounds__(1024)
tail_kernel(const float *__restrict__ d0p, const float *__restrict__ b_d0,
            const float *__restrict__ W_d1, const float *__restrict__ b_d1,
            const float *__restrict__ W_d2, float *__restrict__ out8)
{
    __shared__ float sd0[1024];
    __shared__ float sd1[256];
    __shared__ float sl[8];
    const int tid = threadIdx.x;

    float s = 0.0f;
#pragma unroll
    for (int c = 0; c < 64; c++) s += d0p[c * 1024 + tid];
    s += b_d0[tid];
    sd0[tid] = (s > 0.0f) ? s : 0.0f;
    __syncthreads();

    if (tid < 256) {
        float a0 = 0, a1 = 0, a2 = 0, a3 = 0;
        for (int c = 0; c < 1024; c += 4) {
            a0 = fmaf(sd0[c + 0], W_d1[(c + 0) * 256 + tid], a0);
            a1 = fmaf(sd0[c + 1], W_d1[(c + 1) * 256 + tid], a1);
            a2 = fmaf(sd0[c + 2], W_d1[(c + 2) * 256 + tid], a2);
            a3 = fmaf(sd0[c + 3], W_d1[(c + 3) * 256 + tid], a3);
        }
        float a = ((a0 + a1) + (a2 + a3)) + b_d1[tid];
        sd1[tid] = (a > 0.0f) ? a : 0.0f;
    }
    __syncthreads();

    if (tid < 8) {
        float a = 0.0f;
        for (int c = 0; c < 256; c++) a = fmaf(sd1[c], W_d2[c * 8 + tid], a);
        sl[tid] = a;
    }
    __syncthreads();

    if (tid == 0) {
        float mx = sl[0];
#pragma unroll
        for (int k = 1; k < 8; k++) mx = fmaxf(mx, sl[k]);
        float e[8], sum = 0.0f;
#pragma unroll
        for (int k = 0; k < 8; k++) { e[k] = expf(sl[k] - mx); sum += e[k]; }
#pragma unroll
        for (int k = 0; k < 8; k++) out8[k] = e[k] / sum;
    }
}

// ---------------- launcher ---------------------------------------------------
extern "C" void kernel_launch(void *const *d_in, const int *in_sizes, int n_in,
                              void *d_out, int out_size)
{
    const float *F_      = (const float *)d_in[0];
    const float *X       = (const float *)d_in[1];
    const float *We0     = (const float *)d_in[2];
    const float *be0     = (const float *)d_in[3];
    const float *We1     = (const float *)d_in[4];
    const float *be1     = (const float *)d_in[5];
    const float *We2     = (const float *)d_in[6];
    const float *be2     = (const float *)d_in[7];
    const float *Wd0     = (const float *)d_in[8];
    const float *bd0     = (const float *)d_in[9];
    const float *Wd1     = (const float *)d_in[10];
    const float *bd1     = (const float *)d_in[11];
    const float *Wd2     = (const float *)d_in[12];
    const float *pf      = (const float *)d_in[13];
    const float *members = (const float *)d_in[14];

    float *out      = (float *)d_out;
    float *outF     = out;                                   // new_features [8192,64]
    float *outForce = out + (long long)NN * 64;              // new_force [8192,8192]
    float *out8     = out + (long long)NN * 64 + (long long)NN * NN;  // output [8]

    void *p;
    cudaGetSymbolAddress(&p, g_inp); float *pinp = (float *)p;
    cudaGetSymbolAddress(&p, g_h0);  float *ph0  = (float *)p;
    cudaGetSymbolAddress(&p, g_h1);  float *ph1  = (float *)p;
    cudaGetSymbolAddress(&p, g_n2);  float *pn2  = (float *)p;
    cudaGetSymbolAddress(&p, g_Fg);  float *pFg  = (float *)p;
    cudaGetSymbolAddress(&p, g_d0p); float *pd0p = (float *)p;

    // 1) inp = F_ @ X                         [8192,256] = [8192,8192]@[8192,256]
    gemm_kernel<128, 128, 32, 8, 8, 0><<<dim3(2, 64), 256>>>(F_, X, nullptr, pinp, NN, 256, NN);
    // 2) h0 = tanh(inp @ W_e0 + b_e0)         [8192,256]
    gemm_kernel<128, 128, 32, 8, 8, 1><<<dim3(2, 64), 256>>>(pinp, We0, be0, ph0, NN, 256, 256);
    // 3) h1 = tanh(h0 @ W_e1 + b_e1)          [8192,128]
    gemm_kernel<128, 128, 32, 8, 8, 1><<<dim3(1, 64), 256>>>(ph0, We1, be1, ph1, NN, 128, 256);
    // 4) E = h1 @ W_e2 + b_e2  -> d_out       [8192,64]
    gemm_kernel<128, 64, 32, 8, 4, 0><<<dim3(1, 64), 256>>>(ph1, We2, be2, outF, NN, 64, 128);
    // 5) row norms
    n2_kernel<<<NN / 256, 256>>>(outF, pn2);
    // 6) new_force = dist(E) * path_forces -> d_out
    dist_kernel<<<dim3(64, 64), 256>>>(outF, pn2, pf, outForce);
    // 7) Fg = new_force @ members
    fg_kernel<<<NN, 256>>>(outForce, members, pFg);
    // 8) d0 partials over 64 row-chunks of W_d0
    d0_kernel<<<dim3(4, 64), 256>>>(pFg, Wd0, pd0p);
    // 9) reduce + MLP tail + softmax -> last 8 outputs
    tail_kernel<<<1, 1024>>>(pd0p, bd0, Wd1, bd1, Wd2, out8);
}

// round 17
// speedup vs baseline: 1.4945x; 1.4945x over previous
#include <cuda_runtime.h>
#include <cuda_bf16.h>
#include <cstdint>

#define NN   8192
#define KCOM 8

// ---------------- scratch (device globals; no allocations) ------------------
__device__ __align__(256) float g_inp[NN * 256];
__device__ __align__(256) float g_h0 [NN * 256];
__device__ __align__(256) float g_h1 [NN * 128];
__device__ __align__(256) float g_n2 [NN];
__device__ __align__(256) float g_Fg [NN * KCOM];
__device__ __align__(256) float g_d0p[64 * 1024];
__device__ __align__(256) __nv_bfloat16 g_xth[256 * NN];  // X^T hi [256,8192]
__device__ __align__(256) __nv_bfloat16 g_xtl[256 * NN];  // X^T lo
__device__ __align__(256) __nv_bfloat16 g_eh [NN * 64];   // E hi
__device__ __align__(256) __nv_bfloat16 g_el [NN * 64];   // E lo

typedef unsigned long long ull;
typedef uint32_t u32;

// pack two f32 -> bf16x2 (first arg -> low half)
__device__ __forceinline__ u32 pack_bf16x2(float lo, float hi) {
    u32 r;
    asm("cvt.rn.bf16x2.f32 %0, %1, %2;" : "=r"(r) : "f"(hi), "f"(lo));
    return r;
}

// warp MMA: D += A(16x16 row) * B(16x8 col), bf16 in, fp32 acc
__device__ __forceinline__ void mma_bf16(float* c, u32 a0, u32 a1, u32 a2, u32 a3,
                                         u32 b0, u32 b1) {
    asm volatile(
        "mma.sync.aligned.m16n8k16.row.col.f32.bf16.bf16.f32 "
        "{%0,%1,%2,%3}, {%4,%5,%6,%7}, {%8,%9}, {%0,%1,%2,%3};"
        : "+f"(c[0]), "+f"(c[1]), "+f"(c[2]), "+f"(c[3])
        : "r"(a0), "r"(a1), "r"(a2), "r"(a3), "r"(b0), "r"(b1));
}

// ---------------- packed f32x2 SIMT helpers ---------------------------------
__device__ __forceinline__ ull pack2(float lo, float hi) {
    ull u; asm("mov.b64 %0, {%1, %2};" : "=l"(u) : "f"(lo), "f"(hi)); return u;
}
__device__ __forceinline__ void unpack2(ull u, float &lo, float &hi) {
    asm("mov.b64 {%0, %1}, %2;" : "=f"(lo), "=f"(hi) : "l"(u));
}
__device__ __forceinline__ ull fma2(ull a, ull b, ull c) {
    ull d; asm("fma.rn.f32x2 %0, %1, %2, %3;" : "=l"(d) : "l"(a), "l"(b), "l"(c)); return d;
}

// ---------------- conversions ------------------------------------------------
__global__ void xt_conv_kernel(const float* __restrict__ X,
                               __nv_bfloat16* __restrict__ hi,
                               __nv_bfloat16* __restrict__ lo)
{
    __shared__ float t[32][33];
    int k0 = blockIdx.x * 32, n0 = blockIdx.y * 32;
    int tx = threadIdx.x, ty = threadIdx.y;
    t[ty][tx] = X[(long long)(k0 + ty) * 256 + n0 + tx];
    __syncthreads();
    float v = t[tx][ty];
    long long o = (long long)(n0 + ty) * NN + k0 + tx;
    __nv_bfloat16 h = __float2bfloat16(v);
    hi[o] = h;
    lo[o] = __float2bfloat16(v - __bfloat162float(h));
}

__global__ void e_conv_kernel(const float* __restrict__ E,
                              __nv_bfloat16* __restrict__ eh,
                              __nv_bfloat16* __restrict__ el)
{
    int i = blockIdx.x * 256 + threadIdx.x;
    float v = E[i];
    __nv_bfloat16 h = __float2bfloat16(v);
    eh[i] = h;
    el[i] = __float2bfloat16(v - __bfloat162float(h));
}

// ---------------- GEMM1: inp = F_ @ X  (mma.sync, split-bf16) ----------------
// CTA: 64 rows x 256 cols (full N). 512 thr = 16 warps (4x4), warp tile 16x64.
// SMEM (bytes): AH[b]=b*5120, AL[b]=10240+b*5120, BH[b]=20480+b*20480,
//               BL[b]=61440+b*20480.  A rows padded to 40 bf16, B rows too.
#define G1_SMEM 102400
__global__ void __launch_bounds__(512)
gemm1_mma(const float* __restrict__ A, const __nv_bfloat16* __restrict__ Bth,
          const __nv_bfloat16* __restrict__ Btl, float* __restrict__ C)
{
    extern __shared__ char sm[];
    const int tid = threadIdx.x, lane = tid & 31, wid = tid >> 5;
    const int m0 = blockIdx.x * 64;
    const int wm = (wid >> 2) << 4;     // 0,16,32,48
    const int wn = (wid & 3) << 6;      // 0,64,128,192

    const int ar = tid >> 3, akq = tid & 7;   // A loader: row, float4 idx
    const int bn = tid >> 1, bkq = tid & 1;   // B loader: row n, 16-bf16 half

    float acc[8][4];
#pragma unroll
    for (int j = 0; j < 8; j++) { acc[j][0] = acc[j][1] = acc[j][2] = acc[j][3] = 0.f; }

    float4 aReg;
    uint4 bh0R, bh1R, bl0R, bl1R;
    const float* aBase = A + (long long)(m0 + ar) * NN + akq * 4;
    const __nv_bfloat16* bhBase = Bth + (long long)bn * NN + bkq * 16;
    const __nv_bfloat16* blBase = Btl + (long long)bn * NN + bkq * 16;

#define G1_LDG(it) { \
    aReg = *reinterpret_cast<const float4*>(aBase + (it) * 32); \
    const uint4* ph = reinterpret_cast<const uint4*>(bhBase + (it) * 32); \
    bh0R = ph[0]; bh1R = ph[1]; \
    const uint4* pl = reinterpret_cast<const uint4*>(blBase + (it) * 32); \
    bl0R = pl[0]; bl1R = pl[1]; }

#define G1_STS(b) { \
    u32 pA = pack_bf16x2(aReg.x, aReg.y); \
    u32 pB = pack_bf16x2(aReg.z, aReg.w); \
    float h0 = __uint_as_float(pA << 16); \
    float h1 = __uint_as_float(pA & 0xffff0000u); \
    float h2 = __uint_as_float(pB << 16); \
    float h3 = __uint_as_float(pB & 0xffff0000u); \
    u32 lA = pack_bf16x2(aReg.x - h0, aReg.y - h1); \
    u32 lB = pack_bf16x2(aReg.z - h2, aReg.w - h3); \
    *reinterpret_cast<uint2*>(sm + (b) * 5120 + ar * 80 + akq * 8) = make_uint2(pA, pB); \
    *reinterpret_cast<uint2*>(sm + 10240 + (b) * 5120 + ar * 80 + akq * 8) = make_uint2(lA, lB); \
    *reinterpret_cast<uint4*>(sm + 20480 + (b) * 20480 + bn * 80 + bkq * 32) = bh0R; \
    *reinterpret_cast<uint4*>(sm + 20480 + (b) * 20480 + bn * 80 + bkq * 32 + 16) = bh1R; \
    *reinterpret_cast<uint4*>(sm + 61440 + (b) * 20480 + bn * 80 + bkq * 32) = bl0R; \
    *reinterpret_cast<uint4*>(sm + 61440 + (b) * 20480 + bn * 80 + bkq * 32 + 16) = bl1R; }

    G1_LDG(0); G1_STS(0); __syncthreads();

    const int rr = lane >> 2, kq = lane & 3;
    for (int it = 0; it < 256; ++it) {
        const int b = it & 1;
        if (it + 1 < 256) G1_LDG(it + 1);
        const u32* Ah = reinterpret_cast<const u32*>(sm + b * 5120);
        const u32* Al = reinterpret_cast<const u32*>(sm + 10240 + b * 5120);
        const u32* Bh = reinterpret_cast<const u32*>(sm + 20480 + b * 20480);
        const u32* Bl = reinterpret_cast<const u32*>(sm + 61440 + b * 20480);
        const int arow = wm + rr;
#pragma unroll
        for (int ks = 0; ks < 2; ++ks) {
            const int kb = ks * 8 + kq;      // b32 index in padded-40 row
            u32 ah0 = Ah[arow * 20 + kb];
            u32 ah1 = Ah[(arow + 8) * 20 + kb];
            u32 ah2 = Ah[arow * 20 + kb + 4];
            u32 ah3 = Ah[(arow + 8) * 20 + kb + 4];
            u32 al0 = Al[arow * 20 + kb];
            u32 al1 = Al[(arow + 8) * 20 + kb];
            u32 al2 = Al[arow * 20 + kb + 4];
            u32 al3 = Al[(arow + 8) * 20 + kb + 4];
#pragma unroll
            for (int j = 0; j < 8; ++j) {
                const int brow = wn + j * 8 + rr;
                u32 b0 = Bh[brow * 20 + kb];
                u32 b1 = Bh[brow * 20 + kb + 4];
                u32 c0 = Bl[brow * 20 + kb];
                u32 c1 = Bl[brow * 20 + kb + 4];
                mma_bf16(acc[j], ah0, ah1, ah2, ah3, b0, b1);
                mma_bf16(acc[j], ah0, ah1, ah2, ah3, c0, c1);
                mma_bf16(acc[j], al0, al1, al2, al3, b0, b1);
            }
        }
        if (it + 1 < 256) G1_STS(1 - b);
        __syncthreads();
    }

    const int r0 = m0 + wm + rr;
    const int cb = wn + kq * 2;
#pragma unroll
    for (int j = 0; j < 8; ++j) {
        int col = cb + j * 8;
        *reinterpret_cast<float2*>(C + (long long)r0 * 256 + col) =
            make_float2(acc[j][0], acc[j][1]);
        *reinterpret_cast<float2*>(C + (long long)(r0 + 8) * 256 + col) =
            make_float2(acc[j][2], acc[j][3]);
    }
#undef G1_LDG
#undef G1_STS
}

// ---------------- dist: force = sqrt(max(n2i+n2j-2*E@E^T,0))*pf (mma.sync) ---
// CTA 128x128; 256 thr = 8 warps (2x4), warp tile 64x32. K=64 single shot.
// SMEM: AH=0, AL=18432, BH=36864, BL=55296 (rows padded 72 bf16 = 36 b32),
//       n2j at 73728.
#define DS_SMEM 74240
__global__ void __launch_bounds__(256)
dist_mma(const __nv_bfloat16* __restrict__ Eh, const __nv_bfloat16* __restrict__ El,
         const float* __restrict__ n2, const float* __restrict__ pf,
         float* __restrict__ force)
{
    extern __shared__ char sm[];
    const int tid = threadIdx.x, lane = tid & 31, wid = tid >> 5;
    const int i0 = blockIdx.y * 128, j0 = blockIdx.x * 128;

    {
        const int r = tid >> 1, q = tid & 1;
        const uint4* sa_h = reinterpret_cast<const uint4*>(Eh + (long long)(i0 + r) * 64 + q * 32);
        const uint4* sa_l = reinterpret_cast<const uint4*>(El + (long long)(i0 + r) * 64 + q * 32);
        const uint4* sb_h = reinterpret_cast<const uint4*>(Eh + (long long)(j0 + r) * 64 + q * 32);
        const uint4* sb_l = reinterpret_cast<const uint4*>(El + (long long)(j0 + r) * 64 + q * 32);
        uint4* da_h = reinterpret_cast<uint4*>(sm + r * 144 + q * 64);
        uint4* da_l = reinterpret_cast<uint4*>(sm + 18432 + r * 144 + q * 64);
        uint4* db_h = reinterpret_cast<uint4*>(sm + 36864 + r * 144 + q * 64);
        uint4* db_l = reinterpret_cast<uint4*>(sm + 55296 + r * 144 + q * 64);
#pragma unroll
        for (int c = 0; c < 4; c++) {
            da_h[c] = sa_h[c]; da_l[c] = sa_l[c];
            db_h[c] = sb_h[c]; db_l[c] = sb_l[c];
        }
        if (tid < 128) reinterpret_cast<float*>(sm + 73728)[tid] = n2[j0 + tid];
    }
    __syncthreads();

    const u32* Ah = reinterpret_cast<const u32*>(sm);
    const u32* Al = reinterpret_cast<const u32*>(sm + 18432);
    const u32* Bh = reinterpret_cast<const u32*>(sm + 36864);
    const u32* Bl = reinterpret_cast<const u32*>(sm + 55296);
    const float* sn2 = reinterpret_cast<const float*>(sm + 73728);

    const int wm = (wid >> 2) * 64;   // 0 or 64
    const int wn = (wid & 3) * 32;
    const int rr = lane >> 2, kq = lane & 3;

    float acc[4][4][4];
#pragma unroll
    for (int i = 0; i < 4; i++)
#pragma unroll
        for (int j = 0; j < 4; j++)
#pragma unroll
            for (int c = 0; c < 4; c++) acc[i][j][c] = 0.f;

#pragma unroll
    for (int ks = 0; ks < 4; ++ks) {
        const int kb = ks * 8 + kq;
#pragma unroll
        for (int i = 0; i < 4; ++i) {
            const int arow = wm + i * 16 + rr;
            u32 ah0 = Ah[arow * 36 + kb];
            u32 ah1 = Ah[(arow + 8) * 36 + kb];
            u32 ah2 = Ah[arow * 36 + kb + 4];
            u32 ah3 = Ah[(arow + 8) * 36 + kb + 4];
            u32 al0 = Al[arow * 36 + kb];
            u32 al1 = Al[(arow + 8) * 36 + kb];
            u32 al2 = Al[arow * 36 + kb + 4];
            u32 al3 = Al[(arow + 8) * 36 + kb + 4];
#pragma unroll
            for (int j = 0; j < 4; ++j) {
                const int brow = wn + j * 8 + rr;
                u32 b0 = Bh[brow * 36 + kb];
                u32 b1 = Bh[brow * 36 + kb + 4];
                u32 c0 = Bl[brow * 36 + kb];
                u32 c1 = Bl[brow * 36 + kb + 4];
                mma_bf16(acc[i][j], ah0, ah1, ah2, ah3, b0, b1);
                mma_bf16(acc[i][j], ah0, ah1, ah2, ah3, c0, c1);
                mma_bf16(acc[i][j], al0, al1, al2, al3, b0, b1);
            }
        }
    }

#pragma unroll
    for (int i = 0; i < 4; ++i) {
        const int ra = i0 + wm + i * 16 + rr;
        const float n2a = n2[ra], n2b = n2[ra + 8];
#pragma unroll
        for (int j = 0; j < 4; ++j) {
            const int cc = wn + j * 8 + kq * 2;
            const float c0 = sn2[cc], c1 = sn2[cc + 1];
            const long long o0 = (long long)ra * NN + j0 + cc;
            const long long o1 = (long long)(ra + 8) * NN + j0 + cc;
            float2 p0 = *reinterpret_cast<const float2*>(pf + o0);
            float2 p1 = *reinterpret_cast<const float2*>(pf + o1);
            float sq; float2 w;
            sq = n2a + c0 - 2.f * acc[i][j][0]; w.x = (sq > 0.f ? sqrtf(sq) : 0.f) * p0.x;
            sq = n2a + c1 - 2.f * acc[i][j][1]; w.y = (sq > 0.f ? sqrtf(sq) : 0.f) * p0.y;
            *reinterpret_cast<float2*>(force + o0) = w;
            sq = n2b + c0 - 2.f * acc[i][j][2]; w.x = (sq > 0.f ? sqrtf(sq) : 0.f) * p1.x;
            sq = n2b + c1 - 2.f * acc[i][j][3]; w.y = (sq > 0.f ? sqrtf(sq) : 0.f) * p1.y;
            *reinterpret_cast<float2*>(force + o1) = w;
        }
    }
}

// ---------------- SIMT GEMM (encoder layers 2-4) -----------------------------
template <int BM, int BN, int BK, int TM, int TN, int ACT>
__global__ void __launch_bounds__((BM / TM) * (BN / TN))
gemm_kernel(const float *__restrict__ A, const float *__restrict__ B,
            const float *__restrict__ bias, float *__restrict__ C,
            int M, int N, int K)
{
    constexpr int TX = BN / TN, TY = BM / TM, NT = TX * TY;
    __shared__ float As[BK][BM];
    __shared__ float Bs[BK][BN];
    const int tid = threadIdx.x, tx = tid % TX, ty = tid / TX;
    const int m0 = blockIdx.y * BM, n0 = blockIdx.x * BN;

    ull acc[TM][TN / 2];
#pragma unroll
    for (int r = 0; r < TM; r++)
#pragma unroll
        for (int p = 0; p < TN / 2; p++) acc[r][p] = 0ull;

    for (int k0 = 0; k0 < K; k0 += BK) {
#pragma unroll
        for (int l = tid * 4; l < BM * BK; l += NT * 4) {
            int r = l / BK, kk = l % BK;
            float4 v = *reinterpret_cast<const float4 *>(&A[(long long)(m0 + r) * K + k0 + kk]);
            As[kk + 0][r] = v.x; As[kk + 1][r] = v.y; As[kk + 2][r] = v.z; As[kk + 3][r] = v.w;
        }
#pragma unroll
        for (int l = tid * 4; l < BK * BN; l += NT * 4) {
            int kk = l / BN, j = l % BN;
            *reinterpret_cast<float4 *>(&Bs[kk][j]) =
                *reinterpret_cast<const float4 *>(&B[(long long)(k0 + kk) * N + n0 + j]);
        }
        __syncthreads();
#pragma unroll
        for (int kk = 0; kk < BK; kk++) {
            float a[TM]; ull bp[TN / 2];
#pragma unroll
            for (int r = 0; r < TM; r++) a[r] = As[kk][ty * TM + r];
#pragma unroll
            for (int p = 0; p < TN / 2; p++) {
                float2 b2 = *reinterpret_cast<const float2 *>(&Bs[kk][tx * TN + 2 * p]);
                bp[p] = pack2(b2.x, b2.y);
            }
#pragma unroll
            for (int r = 0; r < TM; r++) {
                ull ap = pack2(a[r], a[r]);
#pragma unroll
                for (int p = 0; p < TN / 2; p++) acc[r][p] = fma2(ap, bp[p], acc[r][p]);
            }
        }
        __syncthreads();
    }
#pragma unroll
    for (int r = 0; r < TM; r++) {
        long long row = m0 + ty * TM + r;
#pragma unroll
        for (int p = 0; p < TN / 2; p++) {
            float x0, x1;
            unpack2(acc[r][p], x0, x1);
            int col = n0 + tx * TN + 2 * p;
            if (bias) { x0 += bias[col]; x1 += bias[col + 1]; }
            if (ACT == 1) { x0 = tanhf(x0); x1 = tanhf(x1); }
            C[row * N + col] = x0;
            C[row * N + col + 1] = x1;
        }
    }
}

// ---------------- row norms --------------------------------------------------
__global__ void n2_kernel(const float *__restrict__ E, float *__restrict__ n2)
{
    int i = blockIdx.x * blockDim.x + threadIdx.x;
    if (i < NN) {
        const float *row = E + (long long)i * 64;
        float acc = 0.0f;
#pragma unroll
        for (int k = 0; k < 64; k++) acc = fmaf(row[k], row[k], acc);
        n2[i] = acc;
    }
}

// ---------------- Fg = force @ members ---------------------------------------
__global__ void __launch_bounds__(256)
fg_kernel(const float *__restrict__ force, const float *__restrict__ members,
          float *__restrict__ Fg)
{
    const int i = blockIdx.x, tid = threadIdx.x;
    const float *frow = force + (long long)i * NN;
    float acc[8] = {0, 0, 0, 0, 0, 0, 0, 0};
    for (int j = tid; j < NN; j += 256) {
        float f = frow[j];
        float4 m0 = *reinterpret_cast<const float4 *>(&members[j * 8]);
        float4 m1 = *reinterpret_cast<const float4 *>(&members[j * 8 + 4]);
        acc[0] = fmaf(f, m0.x, acc[0]); acc[1] = fmaf(f, m0.y, acc[1]);
        acc[2] = fmaf(f, m0.z, acc[2]); acc[3] = fmaf(f, m0.w, acc[3]);
        acc[4] = fmaf(f, m1.x, acc[4]); acc[5] = fmaf(f, m1.y, acc[5]);
        acc[6] = fmaf(f, m1.z, acc[6]); acc[7] = fmaf(f, m1.w, acc[7]);
    }
#pragma unroll
    for (int k = 0; k < 8; k++)
#pragma unroll
        for (int off = 16; off > 0; off >>= 1)
            acc[k] += __shfl_down_sync(0xffffffffu, acc[k], off);
    __shared__ float red[8][8];
    int lane = tid & 31, w = tid >> 5;
    if (lane == 0)
#pragma unroll
        for (int k = 0; k < 8; k++) red[w][k] = acc[k];
    __syncthreads();
    if (tid < 8) {
        float s = 0.0f;
#pragma unroll
        for (int w2 = 0; w2 < 8; w2++) s += red[w2][tid];
        Fg[i * 8 + tid] = s;
    }
}

// ---------------- d0 GEMV partials -------------------------------------------
__global__ void __launch_bounds__(256)
d0_kernel(const float *__restrict__ Fg, const float *__restrict__ Wd0,
          float *__restrict__ d0p)
{
    __shared__ float sv[1024];
    const int tid = threadIdx.x;
    const int m0 = blockIdx.y * 1024;
    const int c = blockIdx.x * 256 + tid;
#pragma unroll
    for (int s = 0; s < 4; s++) sv[tid + 256 * s] = Fg[m0 + tid + 256 * s];
    __syncthreads();
    float a0 = 0, a1 = 0, a2 = 0, a3 = 0;
    const float *W = Wd0 + (long long)m0 * 1024 + c;
    for (int m = 0; m < 1024; m += 4) {
        a0 = fmaf(sv[m + 0], W[(long long)(m + 0) * 1024], a0);
        a1 = fmaf(sv[m + 1], W[(long long)(m + 1) * 1024], a1);
        a2 = fmaf(sv[m + 2], W[(long long)(m + 2) * 1024], a2);
        a3 = fmaf(sv[m + 3], W[(long long)(m + 3) * 1024], a3);
    }
    d0p[blockIdx.y * 1024 + c] = (a0 + a1) + (a2 + a3);
}

// ---------------- tail --------------------------------------------------------
__global__ void __launch_bounds__(1024)
tail_kernel(const float *__restrict__ d0p, const float *__restrict__ b_d0,
            const float *__restrict__ W_d1, const float *__restrict__ b_d1,
            const float *__restrict__ W_d2, float *__restrict__ out8)
{
    __shared__ float sd0[1024];
    __shared__ float sd1[256];
    __shared__ float sl[8];
    const int tid = threadIdx.x;
    float s = 0.0f;
#pragma unroll
    for (int c = 0; c < 64; c++) s += d0p[c * 1024 + tid];
    s += b_d0[tid];
    sd0[tid] = (s > 0.0f) ? s : 0.0f;
    __syncthreads();
    if (tid < 256) {
        float a0 = 0, a1 = 0, a2 = 0, a3 = 0;
        for (int c = 0; c < 1024; c += 4) {
            a0 = fmaf(sd0[c + 0], W_d1[(c + 0) * 256 + tid], a0);
            a1 = fmaf(sd0[c + 1], W_d1[(c + 1) * 256 + tid], a1);
            a2 = fmaf(sd0[c + 2], W_d1[(c + 2) * 256 + tid], a2);
            a3 = fmaf(sd0[c + 3], W_d1[(c + 3) * 256 + tid], a3);
        }
        float a = ((a0 + a1) + (a2 + a3)) + b_d1[tid];
        sd1[tid] = (a > 0.0f) ? a : 0.0f;
    }
    __syncthreads();
    if (tid < 8) {
        float a = 0.0f;
        for (int c = 0; c < 256; c++) a = fmaf(sd1[c], W_d2[c * 8 + tid], a);
        sl[tid] = a;
    }
    __syncthreads();
    if (tid == 0) {
        float mx = sl[0];
#pragma unroll
        for (int k = 1; k < 8; k++) mx = fmaxf(mx, sl[k]);
        float e[8], sum = 0.0f;
#pragma unroll
        for (int k = 0; k < 8; k++) { e[k] = expf(sl[k] - mx); sum += e[k]; }
#pragma unroll
        for (int k = 0; k < 8; k++) out8[k] = e[k] / sum;
    }
}

// ---------------- launcher ----------------------------------------------------
extern "C" void kernel_launch(void *const *d_in, const int *in_sizes, int n_in,
                              void *d_out, int out_size)
{
    const float *F_  = (const float *)d_in[0];
    const float *X   = (const float *)d_in[1];
    const float *We0 = (const float *)d_in[2];
    const float *be0 = (const float *)d_in[3];
    const float *We1 = (const float *)d_in[4];
    const float *be1 = (const float *)d_in[5];
    const float *We2 = (const float *)d_in[6];
    const float *be2 = (const float *)d_in[7];
    const float *Wd0 = (const float *)d_in[8];
    const float *bd0 = (const float *)d_in[9];
    const float *Wd1 = (const float *)d_in[10];
    const float *bd1 = (const float *)d_in[11];
    const float *Wd2 = (const float *)d_in[12];
    const float *pf  = (const float *)d_in[13];
    const float *members = (const float *)d_in[14];

    float *out      = (float *)d_out;
    float *outF     = out;
    float *outForce = out + (long long)NN * 64;
    float *out8     = out + (long long)NN * 64 + (long long)NN * NN;

    void *p;
    cudaGetSymbolAddress(&p, g_inp); float *pinp = (float *)p;
    cudaGetSymbolAddress(&p, g_h0);  float *ph0  = (float *)p;
    cudaGetSymbolAddress(&p, g_h1);  float *ph1  = (float *)p;
    cudaGetSymbolAddress(&p, g_n2);  float *pn2  = (float *)p;
    cudaGetSymbolAddress(&p, g_Fg);  float *pFg  = (float *)p;
    cudaGetSymbolAddress(&p, g_d0p); float *pd0p = (float *)p;
    cudaGetSymbolAddress(&p, g_xth); __nv_bfloat16 *pxh = (__nv_bfloat16 *)p;
    cudaGetSymbolAddress(&p, g_xtl); __nv_bfloat16 *pxl = (__nv_bfloat16 *)p;
    cudaGetSymbolAddress(&p, g_eh);  __nv_bfloat16 *peh = (__nv_bfloat16 *)p;
    cudaGetSymbolAddress(&p, g_el);  __nv_bfloat16 *pel = (__nv_bfloat16 *)p;

    cudaFuncSetAttribute(gemm1_mma, cudaFuncAttributeMaxDynamicSharedMemorySize, G1_SMEM);
    cudaFuncSetAttribute(dist_mma,  cudaFuncAttributeMaxDynamicSharedMemorySize, DS_SMEM);

    // 0) X^T split to bf16 hi/lo
    xt_conv_kernel<<<dim3(256, 8), dim3(32, 32)>>>(X, pxh, pxl);
    // 1) inp = F_ @ X  (tensor cores via mma.sync)
    gemm1_mma<<<128, 512, G1_SMEM>>>(F_, pxh, pxl, pinp);
    // 2-4) encoder
    gemm_kernel<128, 128, 32, 8, 8, 1><<<dim3(2, 64), 256>>>(pinp, We0, be0, ph0, NN, 256, 256);
    gemm_kernel<128, 128, 32, 8, 8, 1><<<dim3(1, 64), 256>>>(ph0, We1, be1, ph1, NN, 128, 256);
    gemm_kernel<128, 64, 32, 8, 4, 0><<<dim3(1, 64), 256>>>(ph1, We2, be2, outF, NN, 64, 128);
    // 5) norms + E split
    n2_kernel<<<NN / 256, 256>>>(outF, pn2);
    e_conv_kernel<<<NN * 64 / 256, 256>>>(outF, peh, pel);
    // 6) new_force (tensor cores + fused epilogue)
    dist_mma<<<dim3(64, 64), 256, DS_SMEM>>>(peh, pel, pn2, pf, outForce);
    // 7-9) discriminator
    fg_kernel<<<NN, 256>>>(outForce, members, pFg);
    d0_kernel<<<dim3(4, 64), 256>>>(pFg, Wd0, pd0p);
    tail_kernel<<<1, 1024>>>(pd0p, bd0, Wd1, bd1, Wd2, out8);
}